// round 15
// baseline (speedup 1.0000x reference)
#include <cuda_runtime.h>
#include <cuda_fp16.h>
#include <math_constants.h>
#include <cstdint>

constexpr int B = 32, N = 2000, NPAD = 2048, D = 25088;
constexpr int ITOT = D / 64;     // 392 k-iters (dots)
constexpr int KC   = 18;         // dots k-chunks
constexpr int RIT  = NPAD / 64;  // 32 n-iters (read)

constexpr float EPS = 1e-8f, PI_2C = 3.14159f * 0.5f;

__device__ float  g_part[KC * B * NPAD];
__device__ float  g_msq [KC * NPAD];
__device__ float  g_dot [B * NPAD];
__device__ float  g_ms2 [NPAD];
__device__ float  g_kpart[B * 8];             // key-norm partials [b][chunk]
__device__ uint4  g_kb  [ITOT * 4 * 32 * 2];  // key prepacked in mma-fragment order
__device__ __half g_whi [B * NPAD];           // padding [2000,2048) stays 0
__device__ __half g_wlo [B * NPAD];

__device__ __forceinline__ uint32_t smem_u32(const void* p) {
    uint32_t a;
    asm("{ .reg .u64 t; cvta.to.shared.u64 t, %1; cvt.u32.u64 %0, t; }" : "=r"(a) : "l"(p));
    return a;
}
__device__ __forceinline__ void ldm4(uint32_t& r0, uint32_t& r1, uint32_t& r2, uint32_t& r3, uint32_t a) {
    asm volatile("ldmatrix.sync.aligned.m8n8.x4.shared.b16 {%0,%1,%2,%3}, [%4];"
                 : "=r"(r0), "=r"(r1), "=r"(r2), "=r"(r3) : "r"(a));
}
__device__ __forceinline__ void ldm4t(uint32_t& r0, uint32_t& r1, uint32_t& r2, uint32_t& r3, uint32_t a) {
    asm volatile("ldmatrix.sync.aligned.m8n8.x4.trans.shared.b16 {%0,%1,%2,%3}, [%4];"
                 : "=r"(r0), "=r"(r1), "=r"(r2), "=r"(r3) : "r"(a));
}
__device__ __forceinline__ void mma_h(float* c, uint32_t a0, uint32_t a1, uint32_t a2, uint32_t a3,
                                      uint32_t b0, uint32_t b1) {
    asm volatile("mma.sync.aligned.m16n8k16.row.col.f32.f16.f16.f32 "
                 "{%0,%1,%2,%3}, {%4,%5,%6,%7}, {%8,%9}, {%0,%1,%2,%3};"
                 : "+f"(c[0]), "+f"(c[1]), "+f"(c[2]), "+f"(c[3])
                 : "r"(a0), "r"(a1), "r"(a2), "r"(a3), "r"(b0), "r"(b1));
}
__device__ __forceinline__ uint32_t h2(float a, float b) {
    __half2 h = __floats2half2_rn(a, b);
    return *(uint32_t*)&h;
}

// ---------------------------------------------------------------------------
// Kernel 0: prepack key -> dots B fragments. (R11 verbatim)
// ---------------------------------------------------------------------------
__global__ __launch_bounds__(256) void prepack_kernel(const float* __restrict__ key)
{
    const int gid = blockIdx.x * 256 + threadIdx.x;
    const int t = gid & 31, s = gid >> 5;
    const int d = (s >> 2) * 64 + (s & 3) * 16 + 2 * (t & 3);
    uint32_t v0[4], v1[4];
    #pragma unroll
    for (int nf = 0; nf < 4; nf++) {
        const int row = (t >> 2) + 8 * nf;
        const float2 x0 = *(const float2*)&key[row * D + d];
        const float2 x1 = *(const float2*)&key[row * D + d + 8];
        v0[nf] = h2(x0.x, x0.y);
        v1[nf] = h2(x1.x, x1.y);
    }
    g_kb[(s * 32 + t) * 2    ] = make_uint4(v0[0], v0[1], v0[2], v0[3]);
    g_kb[(s * 32 + t) * 2 + 1] = make_uint4(v1[0], v1[1], v1[2], v1[3]);
}

// ---------------------------------------------------------------------------
// Kernel 0b: key-norm partials, full chip. (R14 verbatim)
// ---------------------------------------------------------------------------
__global__ __launch_bounds__(256) void ksq_kernel(const float* __restrict__ key)
{
    const int c = blockIdx.x, b = blockIdx.y, tid = threadIdx.x;
    __shared__ float red[256];
    const float4* p = (const float4*)(key + b * D + c * (D / 8));
    float s = 0.f;
    for (int i = tid; i < 784; i += 256) {
        const float4 v = p[i];
        s = fmaf(v.x, v.x, fmaf(v.y, v.y, fmaf(v.z, v.z, fmaf(v.w, v.w, s))));
    }
    red[tid] = s; __syncthreads();
    for (int o = 128; o > 0; o >>= 1) { if (tid < o) red[tid] += red[tid + o]; __syncthreads(); }
    if (tid == 0) g_kpart[b * 8 + c] = red[0];
}

// ---------------------------------------------------------------------------
// Kernel 1: dots^T partials + m-norm partials. R11 body; launch bound pins
// regs <= 128 so 2 CTAs/SM stay resident (288 blocks = single fat wave).
// ---------------------------------------------------------------------------
__global__ __launch_bounds__(256, 2) void dots_kernel(const float* __restrict__ mem)
{
    const int tid = threadIdx.x, w = tid >> 5, t = tid & 31;
    const int n0 = blockIdx.x * 128, kc = blockIdx.y;
    const int it0 = kc * ITOT / KC, it1 = (kc + 1) * ITOT / KC;
    const int nst = (it1 - it0) * 4;          // divisible by 4
    const int r0 = n0 + w * 16 + (t >> 2);
    const int qc = 2 * (t & 3);
    const bool ok0 = r0 < N, ok1 = (r0 + 8) < N;
    const float* q0 = mem + (long long)(ok0 ? r0 : 0) * D + it0 * 64 + qc;
    const float* q1 = mem + (long long)(ok1 ? r0 + 8 : 0) * D + it0 * 64 + qc;
    const uint4* kb = g_kb + ((long long)(it0 * 4) * 32 + t) * 2;

    float acc[4][4];
    #pragma unroll
    for (int f = 0; f < 4; f++)
        #pragma unroll
        for (int i = 0; i < 4; i++) acc[f][i] = 0.f;
    float ms0 = 0.f, ms1 = 0.f;

    float2 fa[4][4]; uint4 fb[4][2];
    #pragma unroll
    for (int s = 0; s < 3; s++) {
        const float* a0 = q0 + s * 16;
        const float* a1 = q1 + s * 16;
        fa[s][0] = *(const float2*)a0;
        fa[s][1] = *(const float2*)a1;
        fa[s][2] = *(const float2*)(a0 + 8);
        fa[s][3] = *(const float2*)(a1 + 8);
        fb[s][0] = kb[s * 64];
        fb[s][1] = kb[s * 64 + 1];
    }

    #pragma unroll 4
    for (int j = 0; j < nst; ++j) {
        const int cur = j & 3;
        const int nxt = (j + 3) & 3;
        if (j + 3 < nst) {
            const float* a0 = q0 + (j + 3) * 16;
            const float* a1 = q1 + (j + 3) * 16;
            fa[nxt][0] = *(const float2*)a0;
            fa[nxt][1] = *(const float2*)a1;
            fa[nxt][2] = *(const float2*)(a0 + 8);
            fa[nxt][3] = *(const float2*)(a1 + 8);
            fb[nxt][0] = kb[(j + 3) * 64];
            fb[nxt][1] = kb[(j + 3) * 64 + 1];
        }
        float2 f0 = fa[cur][0], f1 = fa[cur][1], f2v = fa[cur][2], f3 = fa[cur][3];
        if (!ok0) { f0 = make_float2(0.f, 0.f); f2v = make_float2(0.f, 0.f); }
        if (!ok1) { f1 = make_float2(0.f, 0.f); f3 = make_float2(0.f, 0.f); }
        ms0 = fmaf(f0.x, f0.x, fmaf(f0.y, f0.y, ms0));
        ms0 = fmaf(f2v.x, f2v.x, fmaf(f2v.y, f2v.y, ms0));
        ms1 = fmaf(f1.x, f1.x, fmaf(f1.y, f1.y, ms1));
        ms1 = fmaf(f3.x, f3.x, fmaf(f3.y, f3.y, ms1));
        const uint32_t a0 = h2(f0.x, f0.y), a1 = h2(f1.x, f1.y);
        const uint32_t a2 = h2(f2v.x, f2v.y), a3 = h2(f3.x, f3.y);
        const uint4 B0 = fb[cur][0], B1 = fb[cur][1];
        mma_h(acc[0], a0, a1, a2, a3, B0.x, B1.x);
        mma_h(acc[1], a0, a1, a2, a3, B0.y, B1.y);
        mma_h(acc[2], a0, a1, a2, a3, B0.z, B1.z);
        mma_h(acc[3], a0, a1, a2, a3, B0.w, B1.w);
    }

    const int nrow = n0 + w * 16 + (t >> 2);
    #pragma unroll
    for (int nf = 0; nf < 4; nf++) {
        g_part[(kc * B + 8 * nf + qc    ) * NPAD + nrow    ] = acc[nf][0];
        g_part[(kc * B + 8 * nf + qc + 1) * NPAD + nrow    ] = acc[nf][1];
        g_part[(kc * B + 8 * nf + qc    ) * NPAD + nrow + 8] = acc[nf][2];
        g_part[(kc * B + 8 * nf + qc + 1) * NPAD + nrow + 8] = acc[nf][3];
    }
    ms0 += __shfl_xor_sync(0xffffffffu, ms0, 1);
    ms0 += __shfl_xor_sync(0xffffffffu, ms0, 2);
    ms1 += __shfl_xor_sync(0xffffffffu, ms1, 1);
    ms1 += __shfl_xor_sync(0xffffffffu, ms1, 2);
    if ((t & 3) == 0) {
        g_msq[kc * NPAD + n0 + w * 16 + (t >> 2)    ] = ms0;
        g_msq[kc * NPAD + n0 + w * 16 + (t >> 2) + 8] = ms1;
    }
}

// ---------------------------------------------------------------------------
// Kernel 1b: collapse KC partials, float4-wide. Grid 64 x 256.
// Per-component c-order identical to R14 -> bit-identical g_dot/g_ms2.
// ---------------------------------------------------------------------------
__global__ __launch_bounds__(256) void reduce_kernel()
{
    const int v = blockIdx.x * 256 + threadIdx.x;   // float4 index over B*NPAD/4
    float4 s = make_float4(0.f, 0.f, 0.f, 0.f);
    #pragma unroll
    for (int c = 0; c < KC; c++) {
        const float4 p = ((const float4*)g_part)[c * (B * NPAD / 4) + v];
        s.x += p.x; s.y += p.y; s.z += p.z; s.w += p.w;
    }
    ((float4*)g_dot)[v] = s;
    if (v < NPAD / 4) {
        float4 m = make_float4(0.f, 0.f, 0.f, 0.f);
        #pragma unroll
        for (int c = 0; c < KC; c++) {
            const float4 p = ((const float4*)g_msq)[c * (NPAD / 4) + v];
            m.x += p.x; m.y += p.y; m.z += p.z; m.w += p.w;
        }
        ((float4*)g_ms2)[v] = m;
    }
}

// ---------------------------------------------------------------------------
// Kernel 2: tan + softmax -> w split hi/lo fp16. (R14 verbatim)
// ---------------------------------------------------------------------------
__global__ __launch_bounds__(256) void softmax_kernel()
{
    const int b = blockIdx.x, tid = threadIdx.x;
    __shared__ float red[256];
    float ks = 0.f;
    #pragma unroll
    for (int c = 0; c < 8; c++) ks += g_kpart[b * 8 + c];
    const float knorm = fmaxf(sqrtf(ks), EPS);

    float sv[8], lmax = -CUDART_INF_F;
    #pragma unroll
    for (int j = 0; j < 8; j++) {
        const int n = tid + 256 * j;
        if (n < N) {
            const float dot = g_dot[b * NPAD + n];
            const float mn  = fmaxf(sqrtf(g_ms2[n]), EPS);
            sv[j] = tanf((dot / (knorm * mn)) * PI_2C);
            lmax = fmaxf(lmax, sv[j]);
        } else sv[j] = -CUDART_INF_F;
    }
    red[tid] = lmax; __syncthreads();
    for (int o = 128; o > 0; o >>= 1) { if (tid < o) red[tid] = fmaxf(red[tid], red[tid+o]); __syncthreads(); }
    const float mx = red[0];
    __syncthreads();

    float ev[8], ls = 0.f;
    #pragma unroll
    for (int j = 0; j < 8; j++) {
        const int n = tid + 256 * j;
        ev[j] = (n < N) ? expf(sv[j] - mx) : 0.f;
        ls += ev[j];
    }
    red[tid] = ls; __syncthreads();
    for (int o = 128; o > 0; o >>= 1) { if (tid < o) red[tid] += red[tid + o]; __syncthreads(); }
    const float inv = 1.f / red[0];
    #pragma unroll
    for (int j = 0; j < 8; j++) {
        const int n = tid + 256 * j;
        if (n < N) {
            const float wv = ev[j] * inv;
            const __half hi = __float2half(wv);
            g_whi[b * NPAD + n] = hi;
            g_wlo[b * NPAD + n] = __float2half(wv - __half2float(hi));
        }
    }
}

// ---------------------------------------------------------------------------
// Kernel 3: out[b,d] = sum_n w[b,n] m[n,d]. (R7/R11 verbatim, proven 45.2us)
// ---------------------------------------------------------------------------
__global__ __launch_bounds__(256) void read_kernel(
    const float* __restrict__ mem, float* __restrict__ out)
{
    extern __shared__ __align__(16) char sm[];
    __half* Aw = (__half*)sm;                  // [buf][64][72]
    __half* Bt = (__half*)(sm + 18432);        // [buf][64][72]
    float*  red = (float*)sm;                  // epilogue reuse (8KB)
    const uint32_t sbA = smem_u32(Aw), sbB = smem_u32(Bt);
    const int tid = threadIdx.x, w = tid >> 5, t = tid & 31;
    const int d0 = blockIdx.x * 64;
    const int mi = w >> 2, nj = w & 3;
    const int wr = tid >> 3, ch = tid & 7;

    uint4 rAh, rAl; float4 rB[4];
    {
        rAh = *(const uint4*)&g_whi[wr * NPAD + ch * 8];
        rAl = *(const uint4*)&g_wlo[wr * NPAD + ch * 8];
        #pragma unroll
        for (int p = 0; p < 4; p++) {
            const int idx = tid + 256 * p, row = idx >> 4, c4 = idx & 15;
            rB[p] = (row < N) ? *(const float4*)&mem[(long long)row * D + d0 + c4 * 4]
                              : make_float4(0.f, 0.f, 0.f, 0.f);
        }
    }

    float acc[2][2][4];
    #pragma unroll
    for (int af = 0; af < 2; af++)
        #pragma unroll
        for (int bf = 0; bf < 2; bf++)
            #pragma unroll
            for (int i = 0; i < 4; i++) acc[af][bf][i] = 0.f;

    for (int it = 0; it < RIT; ++it) {
        const int buf = it & 1;
        __half* A  = Aw + buf * 64 * 72;
        __half* Bm = Bt + buf * 64 * 72;
        *(uint4*)&A[wr * 72 + ch * 8]        = rAh;
        *(uint4*)&A[(32 + wr) * 72 + ch * 8] = rAl;
        #pragma unroll
        for (int p = 0; p < 4; p++) {
            const int idx = tid + 256 * p, row = idx >> 4, c4 = idx & 15;
            *(uint2*)&Bm[row * 72 + c4 * 4] = make_uint2(h2(rB[p].x, rB[p].y), h2(rB[p].z, rB[p].w));
        }
        __syncthreads();
        if (it + 1 < RIT) {
            const int nb = (it + 1) * 64;
            rAh = *(const uint4*)&g_whi[wr * NPAD + nb + ch * 8];
            rAl = *(const uint4*)&g_wlo[wr * NPAD + nb + ch * 8];
            #pragma unroll
            for (int p = 0; p < 4; p++) {
                const int idx = tid + 256 * p, row = idx >> 4, c4 = idx & 15;
                const int n = nb + row;
                rB[p] = (n < N) ? *(const float4*)&mem[(long long)n * D + d0 + c4 * 4]
                                : make_float4(0.f, 0.f, 0.f, 0.f);
            }
        }
        const int lr = (t & 7) + 8 * ((t >> 3) & 1);
        const int lh = 8 * (t >> 4);
        #pragma unroll
        for (int kk = 0; kk < 4; kk++) {
            uint32_t a[2][4], bq[4];
            #pragma unroll
            for (int af = 0; af < 2; af++) {
                const uint32_t addr = sbA + 2u * (buf * 64 * 72 + (mi * 32 + af * 16 + lr) * 72 + kk * 16 + lh);
                ldm4(a[af][0], a[af][1], a[af][2], a[af][3], addr);
            }
            {
                const uint32_t addr = sbB + 2u * (buf * 64 * 72 + (kk * 16 + lr) * 72 + nj * 16 + lh);
                ldm4t(bq[0], bq[1], bq[2], bq[3], addr);
            }
            #pragma unroll
            for (int af = 0; af < 2; af++) {
                mma_h(acc[af][0], a[af][0], a[af][1], a[af][2], a[af][3], bq[0], bq[1]);
                mma_h(acc[af][1], a[af][0], a[af][1], a[af][2], a[af][3], bq[2], bq[3]);
            }
        }
        __syncthreads();
    }

    if (mi == 1) {
        #pragma unroll
        for (int af = 0; af < 2; af++)
            #pragma unroll
            for (int bf = 0; bf < 2; bf++)
                #pragma unroll
                for (int i = 0; i < 4; i++)
                    red[(nj * 32 + t) * 16 + af * 8 + bf * 4 + i] = acc[af][bf][i];
    }
    __syncthreads();
    if (mi == 0) {
        #pragma unroll
        for (int af = 0; af < 2; af++)
            #pragma unroll
            for (int bf = 0; bf < 2; bf++) {
                const float c0 = acc[af][bf][0] + red[(nj * 32 + t) * 16 + af * 8 + bf * 4 + 0];
                const float c1 = acc[af][bf][1] + red[(nj * 32 + t) * 16 + af * 8 + bf * 4 + 1];
                const float c2 = acc[af][bf][2] + red[(nj * 32 + t) * 16 + af * 8 + bf * 4 + 2];
                const float c3 = acc[af][bf][3] + red[(nj * 32 + t) * 16 + af * 8 + bf * 4 + 3];
                const int b   = af * 16 + (t >> 2);
                const int col = d0 + nj * 16 + bf * 8 + 2 * (t & 3);
                *(float2*)&out[b * D + col]       = make_float2(c0, c1);
                *(float2*)&out[(b + 8) * D + col] = make_float2(c2, c3);
            }
    }
}

// ---------------------------------------------------------------------------
extern "C" void kernel_launch(void* const* d_in, const int* in_sizes, int n_in,
                              void* d_out, int out_size)
{
    const float* key = (const float*)d_in[0];
    const float* mem = (const float*)d_in[1];
    float* out = (float*)d_out;

    cudaFuncSetAttribute(read_kernel, cudaFuncAttributeMaxDynamicSharedMemorySize, 36864);

    prepack_kernel<<<ITOT * 4 * 32 / 256, 256>>>(key);
    ksq_kernel<<<dim3(8, 32), 256>>>(key);
    dots_kernel<<<dim3(16, KC), 256>>>(mem);
    reduce_kernel<<<B * NPAD / 4 / 256, 256>>>();
    softmax_kernel<<<32, 256>>>();
    read_kernel<<<D / 64, 256, 36864>>>(mem, out);
}

// round 16
// speedup vs baseline: 1.0032x; 1.0032x over previous
#include <cuda_runtime.h>
#include <cuda_fp16.h>
#include <math_constants.h>
#include <cstdint>

constexpr int B = 32, N = 2000, NPAD = 2048, D = 25088;
constexpr int ITOT = D / 64;     // 392 k-iters (dots)
constexpr int KC   = 18;         // dots k-chunks
constexpr int RIT  = NPAD / 64;  // 32 n-iters (read)

constexpr float EPS = 1e-8f, PI_2C = 3.14159f * 0.5f;

__device__ float  g_part[KC * B * NPAD];
__device__ float  g_msq [KC * NPAD];
__device__ float  g_dot2[2 * B * NPAD];       // KC-half partial dots
__device__ float  g_ms22[2 * NPAD];
__device__ float  g_kpart[B * 8];             // key-norm partials [b][chunk]
__device__ uint4  g_kb  [ITOT * 4 * 32 * 2];  // key prepacked in mma-fragment order
__device__ __half g_whi [B * NPAD];           // padding [2000,2048) stays 0
__device__ __half g_wlo [B * NPAD];

__device__ __forceinline__ uint32_t smem_u32(const void* p) {
    uint32_t a;
    asm("{ .reg .u64 t; cvta.to.shared.u64 t, %1; cvt.u32.u64 %0, t; }" : "=r"(a) : "l"(p));
    return a;
}
__device__ __forceinline__ void ldm4(uint32_t& r0, uint32_t& r1, uint32_t& r2, uint32_t& r3, uint32_t a) {
    asm volatile("ldmatrix.sync.aligned.m8n8.x4.shared.b16 {%0,%1,%2,%3}, [%4];"
                 : "=r"(r0), "=r"(r1), "=r"(r2), "=r"(r3) : "r"(a));
}
__device__ __forceinline__ void ldm4t(uint32_t& r0, uint32_t& r1, uint32_t& r2, uint32_t& r3, uint32_t a) {
    asm volatile("ldmatrix.sync.aligned.m8n8.x4.trans.shared.b16 {%0,%1,%2,%3}, [%4];"
                 : "=r"(r0), "=r"(r1), "=r"(r2), "=r"(r3) : "r"(a));
}
__device__ __forceinline__ void mma_h(float* c, uint32_t a0, uint32_t a1, uint32_t a2, uint32_t a3,
                                      uint32_t b0, uint32_t b1) {
    asm volatile("mma.sync.aligned.m16n8k16.row.col.f32.f16.f16.f32 "
                 "{%0,%1,%2,%3}, {%4,%5,%6,%7}, {%8,%9}, {%0,%1,%2,%3};"
                 : "+f"(c[0]), "+f"(c[1]), "+f"(c[2]), "+f"(c[3])
                 : "r"(a0), "r"(a1), "r"(a2), "r"(a3), "r"(b0), "r"(b1));
}
__device__ __forceinline__ uint32_t h2(float a, float b) {
    __half2 h = __floats2half2_rn(a, b);
    return *(uint32_t*)&h;
}

// ---------------------------------------------------------------------------
// Kernel 0: prepack key -> dots B fragments. (R11 verbatim)
// ---------------------------------------------------------------------------
__global__ __launch_bounds__(256) void prepack_kernel(const float* __restrict__ key)
{
    const int gid = blockIdx.x * 256 + threadIdx.x;
    const int t = gid & 31, s = gid >> 5;
    const int d = (s >> 2) * 64 + (s & 3) * 16 + 2 * (t & 3);
    uint32_t v0[4], v1[4];
    #pragma unroll
    for (int nf = 0; nf < 4; nf++) {
        const int row = (t >> 2) + 8 * nf;
        const float2 x0 = *(const float2*)&key[row * D + d];
        const float2 x1 = *(const float2*)&key[row * D + d + 8];
        v0[nf] = h2(x0.x, x0.y);
        v1[nf] = h2(x1.x, x1.y);
    }
    g_kb[(s * 32 + t) * 2    ] = make_uint4(v0[0], v0[1], v0[2], v0[3]);
    g_kb[(s * 32 + t) * 2 + 1] = make_uint4(v1[0], v1[1], v1[2], v1[3]);
}

// ---------------------------------------------------------------------------
// Kernel 0b: key-norm partials, full chip. (R14 verbatim)
// ---------------------------------------------------------------------------
__global__ __launch_bounds__(256) void ksq_kernel(const float* __restrict__ key)
{
    const int c = blockIdx.x, b = blockIdx.y, tid = threadIdx.x;
    __shared__ float red[256];
    const float4* p = (const float4*)(key + b * D + c * (D / 8));
    float s = 0.f;
    for (int i = tid; i < 784; i += 256) {
        const float4 v = p[i];
        s = fmaf(v.x, v.x, fmaf(v.y, v.y, fmaf(v.z, v.z, fmaf(v.w, v.w, s))));
    }
    red[tid] = s; __syncthreads();
    for (int o = 128; o > 0; o >>= 1) { if (tid < o) red[tid] += red[tid + o]; __syncthreads(); }
    if (tid == 0) g_kpart[b * 8 + c] = red[0];
}

// ---------------------------------------------------------------------------
// Kernel 1: dots^T partials + m-norm partials. (R15 verbatim — LB(256,2) win)
// ---------------------------------------------------------------------------
__global__ __launch_bounds__(256, 2) void dots_kernel(const float* __restrict__ mem)
{
    const int tid = threadIdx.x, w = tid >> 5, t = tid & 31;
    const int n0 = blockIdx.x * 128, kc = blockIdx.y;
    const int it0 = kc * ITOT / KC, it1 = (kc + 1) * ITOT / KC;
    const int nst = (it1 - it0) * 4;          // divisible by 4
    const int r0 = n0 + w * 16 + (t >> 2);
    const int qc = 2 * (t & 3);
    const bool ok0 = r0 < N, ok1 = (r0 + 8) < N;
    const float* q0 = mem + (long long)(ok0 ? r0 : 0) * D + it0 * 64 + qc;
    const float* q1 = mem + (long long)(ok1 ? r0 + 8 : 0) * D + it0 * 64 + qc;
    const uint4* kb = g_kb + ((long long)(it0 * 4) * 32 + t) * 2;

    float acc[4][4];
    #pragma unroll
    for (int f = 0; f < 4; f++)
        #pragma unroll
        for (int i = 0; i < 4; i++) acc[f][i] = 0.f;
    float ms0 = 0.f, ms1 = 0.f;

    float2 fa[4][4]; uint4 fb[4][2];
    #pragma unroll
    for (int s = 0; s < 3; s++) {
        const float* a0 = q0 + s * 16;
        const float* a1 = q1 + s * 16;
        fa[s][0] = *(const float2*)a0;
        fa[s][1] = *(const float2*)a1;
        fa[s][2] = *(const float2*)(a0 + 8);
        fa[s][3] = *(const float2*)(a1 + 8);
        fb[s][0] = kb[s * 64];
        fb[s][1] = kb[s * 64 + 1];
    }

    #pragma unroll 4
    for (int j = 0; j < nst; ++j) {
        const int cur = j & 3;
        const int nxt = (j + 3) & 3;
        if (j + 3 < nst) {
            const float* a0 = q0 + (j + 3) * 16;
            const float* a1 = q1 + (j + 3) * 16;
            fa[nxt][0] = *(const float2*)a0;
            fa[nxt][1] = *(const float2*)a1;
            fa[nxt][2] = *(const float2*)(a0 + 8);
            fa[nxt][3] = *(const float2*)(a1 + 8);
            fb[nxt][0] = kb[(j + 3) * 64];
            fb[nxt][1] = kb[(j + 3) * 64 + 1];
        }
        float2 f0 = fa[cur][0], f1 = fa[cur][1], f2v = fa[cur][2], f3 = fa[cur][3];
        if (!ok0) { f0 = make_float2(0.f, 0.f); f2v = make_float2(0.f, 0.f); }
        if (!ok1) { f1 = make_float2(0.f, 0.f); f3 = make_float2(0.f, 0.f); }
        ms0 = fmaf(f0.x, f0.x, fmaf(f0.y, f0.y, ms0));
        ms0 = fmaf(f2v.x, f2v.x, fmaf(f2v.y, f2v.y, ms0));
        ms1 = fmaf(f1.x, f1.x, fmaf(f1.y, f1.y, ms1));
        ms1 = fmaf(f3.x, f3.x, fmaf(f3.y, f3.y, ms1));
        const uint32_t a0 = h2(f0.x, f0.y), a1 = h2(f1.x, f1.y);
        const uint32_t a2 = h2(f2v.x, f2v.y), a3 = h2(f3.x, f3.y);
        const uint4 B0 = fb[cur][0], B1 = fb[cur][1];
        mma_h(acc[0], a0, a1, a2, a3, B0.x, B1.x);
        mma_h(acc[1], a0, a1, a2, a3, B0.y, B1.y);
        mma_h(acc[2], a0, a1, a2, a3, B0.z, B1.z);
        mma_h(acc[3], a0, a1, a2, a3, B0.w, B1.w);
    }

    const int nrow = n0 + w * 16 + (t >> 2);
    #pragma unroll
    for (int nf = 0; nf < 4; nf++) {
        g_part[(kc * B + 8 * nf + qc    ) * NPAD + nrow    ] = acc[nf][0];
        g_part[(kc * B + 8 * nf + qc + 1) * NPAD + nrow    ] = acc[nf][1];
        g_part[(kc * B + 8 * nf + qc    ) * NPAD + nrow + 8] = acc[nf][2];
        g_part[(kc * B + 8 * nf + qc + 1) * NPAD + nrow + 8] = acc[nf][3];
    }
    ms0 += __shfl_xor_sync(0xffffffffu, ms0, 1);
    ms0 += __shfl_xor_sync(0xffffffffu, ms0, 2);
    ms1 += __shfl_xor_sync(0xffffffffu, ms1, 1);
    ms1 += __shfl_xor_sync(0xffffffffu, ms1, 2);
    if ((t & 3) == 0) {
        g_msq[kc * NPAD + n0 + w * 16 + (t >> 2)    ] = ms0;
        g_msq[kc * NPAD + n0 + w * 16 + (t >> 2) + 8] = ms1;
    }
}

// ---------------------------------------------------------------------------
// Kernel 1b: collapse KC partials, scalar (R14 layout) but KC split across
// blockIdx.y in {0,1} -> 512 blocks for latency coverage. Softmax adds halves.
// ---------------------------------------------------------------------------
__global__ __launch_bounds__(256) void reduce_kernel()
{
    const int idx = blockIdx.x * 256 + threadIdx.x;   // b*NPAD + n
    const int h = blockIdx.y;                         // KC half: 0 -> c 0..8, 1 -> c 9..17
    const int c0 = h * 9;
    float s = 0.f;
    #pragma unroll
    for (int c = 0; c < 9; c++) s += g_part[(c0 + c) * B * NPAD + idx];
    g_dot2[h * B * NPAD + idx] = s;
    if (idx < NPAD) {
        float m = 0.f;
        #pragma unroll
        for (int c = 0; c < 9; c++) m += g_msq[(c0 + c) * NPAD + idx];
        g_ms22[h * NPAD + idx] = m;
    }
}

// ---------------------------------------------------------------------------
// Kernel 2: tan + softmax -> w split hi/lo fp16. Adds the two KC halves.
// ---------------------------------------------------------------------------
__global__ __launch_bounds__(256) void softmax_kernel()
{
    const int b = blockIdx.x, tid = threadIdx.x;
    __shared__ float red[256];
    float ks = 0.f;
    #pragma unroll
    for (int c = 0; c < 8; c++) ks += g_kpart[b * 8 + c];
    const float knorm = fmaxf(sqrtf(ks), EPS);

    float sv[8], lmax = -CUDART_INF_F;
    #pragma unroll
    for (int j = 0; j < 8; j++) {
        const int n = tid + 256 * j;
        if (n < N) {
            const float dot = g_dot2[b * NPAD + n] + g_dot2[B * NPAD + b * NPAD + n];
            const float ms  = g_ms22[n] + g_ms22[NPAD + n];
            const float mn  = fmaxf(sqrtf(ms), EPS);
            sv[j] = tanf((dot / (knorm * mn)) * PI_2C);
            lmax = fmaxf(lmax, sv[j]);
        } else sv[j] = -CUDART_INF_F;
    }
    red[tid] = lmax; __syncthreads();
    for (int o = 128; o > 0; o >>= 1) { if (tid < o) red[tid] = fmaxf(red[tid], red[tid+o]); __syncthreads(); }
    const float mx = red[0];
    __syncthreads();

    float ev[8], ls = 0.f;
    #pragma unroll
    for (int j = 0; j < 8; j++) {
        const int n = tid + 256 * j;
        ev[j] = (n < N) ? expf(sv[j] - mx) : 0.f;
        ls += ev[j];
    }
    red[tid] = ls; __syncthreads();
    for (int o = 128; o > 0; o >>= 1) { if (tid < o) red[tid] += red[tid + o]; __syncthreads(); }
    const float inv = 1.f / red[0];
    #pragma unroll
    for (int j = 0; j < 8; j++) {
        const int n = tid + 256 * j;
        if (n < N) {
            const float wv = ev[j] * inv;
            const __half hi = __float2half(wv);
            g_whi[b * NPAD + n] = hi;
            g_wlo[b * NPAD + n] = __float2half(wv - __half2float(hi));
        }
    }
}

// ---------------------------------------------------------------------------
// Kernel 3: out[b,d] = sum_n w[b,n] m[n,d]. (R7/R11 verbatim, proven 45.2us)
// ---------------------------------------------------------------------------
__global__ __launch_bounds__(256) void read_kernel(
    const float* __restrict__ mem, float* __restrict__ out)
{
    extern __shared__ __align__(16) char sm[];
    __half* Aw = (__half*)sm;                  // [buf][64][72]
    __half* Bt = (__half*)(sm + 18432);        // [buf][64][72]
    float*  red = (float*)sm;                  // epilogue reuse (8KB)
    const uint32_t sbA = smem_u32(Aw), sbB = smem_u32(Bt);
    const int tid = threadIdx.x, w = tid >> 5, t = tid & 31;
    const int d0 = blockIdx.x * 64;
    const int mi = w >> 2, nj = w & 3;
    const int wr = tid >> 3, ch = tid & 7;

    uint4 rAh, rAl; float4 rB[4];
    {
        rAh = *(const uint4*)&g_whi[wr * NPAD + ch * 8];
        rAl = *(const uint4*)&g_wlo[wr * NPAD + ch * 8];
        #pragma unroll
        for (int p = 0; p < 4; p++) {
            const int idx = tid + 256 * p, row = idx >> 4, c4 = idx & 15;
            rB[p] = (row < N) ? *(const float4*)&mem[(long long)row * D + d0 + c4 * 4]
                              : make_float4(0.f, 0.f, 0.f, 0.f);
        }
    }

    float acc[2][2][4];
    #pragma unroll
    for (int af = 0; af < 2; af++)
        #pragma unroll
        for (int bf = 0; bf < 2; bf++)
            #pragma unroll
            for (int i = 0; i < 4; i++) acc[af][bf][i] = 0.f;

    for (int it = 0; it < RIT; ++it) {
        const int buf = it & 1;
        __half* A  = Aw + buf * 64 * 72;
        __half* Bm = Bt + buf * 64 * 72;
        *(uint4*)&A[wr * 72 + ch * 8]        = rAh;
        *(uint4*)&A[(32 + wr) * 72 + ch * 8] = rAl;
        #pragma unroll
        for (int p = 0; p < 4; p++) {
            const int idx = tid + 256 * p, row = idx >> 4, c4 = idx & 15;
            *(uint2*)&Bm[row * 72 + c4 * 4] = make_uint2(h2(rB[p].x, rB[p].y), h2(rB[p].z, rB[p].w));
        }
        __syncthreads();
        if (it + 1 < RIT) {
            const int nb = (it + 1) * 64;
            rAh = *(const uint4*)&g_whi[wr * NPAD + nb + ch * 8];
            rAl = *(const uint4*)&g_wlo[wr * NPAD + nb + ch * 8];
            #pragma unroll
            for (int p = 0; p < 4; p++) {
                const int idx = tid + 256 * p, row = idx >> 4, c4 = idx & 15;
                const int n = nb + row;
                rB[p] = (n < N) ? *(const float4*)&mem[(long long)n * D + d0 + c4 * 4]
                                : make_float4(0.f, 0.f, 0.f, 0.f);
            }
        }
        const int lr = (t & 7) + 8 * ((t >> 3) & 1);
        const int lh = 8 * (t >> 4);
        #pragma unroll
        for (int kk = 0; kk < 4; kk++) {
            uint32_t a[2][4], bq[4];
            #pragma unroll
            for (int af = 0; af < 2; af++) {
                const uint32_t addr = sbA + 2u * (buf * 64 * 72 + (mi * 32 + af * 16 + lr) * 72 + kk * 16 + lh);
                ldm4(a[af][0], a[af][1], a[af][2], a[af][3], addr);
            }
            {
                const uint32_t addr = sbB + 2u * (buf * 64 * 72 + (kk * 16 + lr) * 72 + nj * 16 + lh);
                ldm4t(bq[0], bq[1], bq[2], bq[3], addr);
            }
            #pragma unroll
            for (int af = 0; af < 2; af++) {
                mma_h(acc[af][0], a[af][0], a[af][1], a[af][2], a[af][3], bq[0], bq[1]);
                mma_h(acc[af][1], a[af][0], a[af][1], a[af][2], a[af][3], bq[2], bq[3]);
            }
        }
        __syncthreads();
    }

    if (mi == 1) {
        #pragma unroll
        for (int af = 0; af < 2; af++)
            #pragma unroll
            for (int bf = 0; bf < 2; bf++)
                #pragma unroll
                for (int i = 0; i < 4; i++)
                    red[(nj * 32 + t) * 16 + af * 8 + bf * 4 + i] = acc[af][bf][i];
    }
    __syncthreads();
    if (mi == 0) {
        #pragma unroll
        for (int af = 0; af < 2; af++)
            #pragma unroll
            for (int bf = 0; bf < 2; bf++) {
                const float c0 = acc[af][bf][0] + red[(nj * 32 + t) * 16 + af * 8 + bf * 4 + 0];
                const float c1 = acc[af][bf][1] + red[(nj * 32 + t) * 16 + af * 8 + bf * 4 + 1];
                const float c2 = acc[af][bf][2] + red[(nj * 32 + t) * 16 + af * 8 + bf * 4 + 2];
                const float c3 = acc[af][bf][3] + red[(nj * 32 + t) * 16 + af * 8 + bf * 4 + 3];
                const int b   = af * 16 + (t >> 2);
                const int col = d0 + nj * 16 + bf * 8 + 2 * (t & 3);
                *(float2*)&out[b * D + col]       = make_float2(c0, c1);
                *(float2*)&out[(b + 8) * D + col] = make_float2(c2, c3);
            }
    }
}

// ---------------------------------------------------------------------------
extern "C" void kernel_launch(void* const* d_in, const int* in_sizes, int n_in,
                              void* d_out, int out_size)
{
    const float* key = (const float*)d_in[0];
    const float* mem = (const float*)d_in[1];
    float* out = (float*)d_out;

    cudaFuncSetAttribute(read_kernel, cudaFuncAttributeMaxDynamicSharedMemorySize, 36864);

    prepack_kernel<<<ITOT * 4 * 32 / 256, 256>>>(key);
    ksq_kernel<<<dim3(8, 32), 256>>>(key);
    dots_kernel<<<dim3(16, KC), 256>>>(mem);
    reduce_kernel<<<dim3(B * NPAD / 256, 2), 256>>>();
    softmax_kernel<<<32, 256>>>();
    read_kernel<<<D / 64, 256, 36864>>>(mem, out);
}